// round 6
// baseline (speedup 1.0000x reference)
#include <cuda_runtime.h>
#include <math_constants.h>

// Banded DTW (Sakoe-Chiba w=1) as a tropical (min,+) 3x3 matrix product,
// fused single launch. This revision: coalesced float4 loads with front-
// batched MLP=4 per thread (was stride-4 scalar, latency-bound).
//   - thread g folds steps [4g, 4g+4) via two LDG.128 + 2 scalar boundary LDG
//   - order-preserving warp-shuffle tree reduce (later (*) earlier)
//   - last-block-to-finish does the grid-level reduce, writes d[n,n]=P[1][1]

#define NBLK 128
#define NTHR 256
#define NWARP (NTHR / 32)
#define CHUNK 4

__device__ float g_block_mats[NBLK * 9];
__device__ unsigned int g_counter = 0;

struct Mat {
    float m[9];  // row-major [r*3+c]
};

// total = B after A (A earlier): C[r][c] = min_k B[r][k] + A[k][c]
__device__ __forceinline__ Mat mp_mul(const Mat& B, const Mat& A) {
    Mat C;
#pragma unroll
    for (int r = 0; r < 3; r++) {
#pragma unroll
        for (int c = 0; c < 3; c++) {
            float v = B.m[r * 3 + 0] + A.m[0 * 3 + c];
            v = fminf(v, B.m[r * 3 + 1] + A.m[1 * 3 + c]);
            v = fminf(v, B.m[r * 3 + 2] + A.m[2 * 3 + c]);
            C.m[r * 3 + c] = v;
        }
    }
    return C;
}

__device__ __forceinline__ Mat mat_identity() {
    Mat P;
#pragma unroll
    for (int i = 0; i < 9; i++) P.m[i] = CUDART_INF_F;
    P.m[0] = 0.0f; P.m[4] = 0.0f; P.m[8] = 0.0f;
    return P;
}

__device__ __forceinline__ Mat shfl_down_mat(const Mat& P, int s) {
    Mat R;
#pragma unroll
    for (int i = 0; i < 9; i++)
        R.m[i] = __shfl_down_sync(0xFFFFFFFFu, P.m[i], s);
    return R;
}

// Order-preserving warp reduce: after level s, lane t holds the product of the
// contiguous range [t, t+2s) combined as later (*) earlier. Lane 0 ends with
// the full range.
template <int WIDTH>
__device__ __forceinline__ Mat warp_reduce_ordered(Mat P) {
#pragma unroll
    for (int s = 1; s < WIDTH; s <<= 1) {
        Mat other = shfl_down_mat(P, s);  // later range
        P = mp_mul(other, P);
    }
    return P;
}

// Apply one elementary DP step (costs a0,a1,a2, masks) to all 3 basis columns.
__device__ __forceinline__ void apply_step(Mat& P, float a0, float a1, float a2,
                                           bool mask0, bool mask2) {
    const float INF = CUDART_INF_F;
#pragma unroll
    for (int c = 0; c < 3; c++) {
        float p0 = P.m[0 * 3 + c], p1 = P.m[1 * 3 + c], p2 = P.m[2 * 3 + c];
        float n0 = a0 + fminf(p0, p1);
        n0 = mask0 ? INF : n0;
        float n1 = a1 + fminf(n0, fminf(p1, p2));
        float n2 = a2 + fminf(n1, p2);
        n2 = mask2 ? INF : n2;
        P.m[0 * 3 + c] = n0;
        P.m[1 * 3 + c] = n1;
        P.m[2 * 3 + c] = n2;
    }
}

__global__ void dtw_fused(const float* __restrict__ outp,
                          const float* __restrict__ tgt,
                          float* __restrict__ d_out,
                          int n) {
    const int t = threadIdx.x;
    const int lane = t & 31;
    const int warp = t >> 5;
    const int g = blockIdx.x * NTHR + t;
    const int base = g * CHUNK;

    Mat P = mat_identity();

    if (base + CHUNK <= n) {
        // ---- fast path: all loads issued up front (MLP=4, coalesced) ----
        float4 o4 = *reinterpret_cast<const float4*>(outp + base);
        float4 t4 = *reinterpret_cast<const float4*>(tgt + base);
        float tlo = (base > 0) ? tgt[base - 1] : 0.0f;           // masked if base==0
        float thi = (base + CHUNK < n) ? tgt[base + CHUNK] : 0.0f; // masked if last

        float o[CHUNK]  = {o4.x, o4.y, o4.z, o4.w};
        float tm[CHUNK] = {t4.x, t4.y, t4.z, t4.w};
        float tl[CHUNK] = {tlo,  t4.x, t4.y, t4.z};
        float th[CHUNK] = {t4.y, t4.z, t4.w, thi};

#pragma unroll
        for (int j = 0; j < CHUNK; j++) {
            int k = base + j;
            float a0 = fabsf(o[j] - tl[j]);
            float a1 = fabsf(o[j] - tm[j]);
            float a2 = fabsf(o[j] - th[j]);
            apply_step(P, a0, a1, a2, (k == 0), (k == n - 1));
        }
    } else if (base < n) {
        // ---- tail path (n not multiple of CHUNK*grid): scalar ----
        for (int j = 0; j < CHUNK; j++) {
            int k = base + j;
            if (k >= n) break;
            float o  = outp[k];
            float tm = tgt[k];
            float tl = tgt[(k >= 1) ? (k - 1) : 0];
            float th = tgt[(k + 1 < n) ? (k + 1) : (n - 1)];
            float a0 = fabsf(o - tl);
            float a1 = fabsf(o - tm);
            float a2 = fabsf(o - th);
            apply_step(P, a0, a1, a2, (k == 0), (k == n - 1));
        }
    }

    // ---- in-warp ordered reduce ----
    P = warp_reduce_ordered<32>(P);

    // ---- cross-warp reduce through shared ----
    __shared__ float s_warp[NWARP * 9];
    __shared__ bool s_islast;
    if (lane == 0) {
#pragma unroll
        for (int i = 0; i < 9; i++) s_warp[warp * 9 + i] = P.m[i];
    }
    __syncthreads();

    if (warp == 0) {
        Mat W = mat_identity();
        if (lane < NWARP) {
#pragma unroll
            for (int i = 0; i < 9; i++) W.m[i] = s_warp[lane * 9 + i];
        }
        W = warp_reduce_ordered<NWARP>(W);
        if (lane == 0) {
#pragma unroll
            for (int i = 0; i < 9; i++)
                g_block_mats[blockIdx.x * 9 + i] = W.m[i];
            __threadfence();
            unsigned int old = atomicAdd(&g_counter, 1u);
            s_islast = (old == (unsigned int)(gridDim.x - 1));
        }
    }
    __syncthreads();

    // ---- last block: grid-level reduce of NBLK matrices ----
    if (s_islast) {
        Mat F = mat_identity();
        if (t < NBLK) {
#pragma unroll
            for (int i = 0; i < 9; i++) F.m[i] = g_block_mats[t * 9 + i];
        }
        F = warp_reduce_ordered<32>(F);

        __shared__ float s_final[(NBLK / 32) * 9];
        if (lane == 0 && t < NBLK) {
#pragma unroll
            for (int i = 0; i < 9; i++) s_final[warp * 9 + i] = F.m[i];
        }
        __syncthreads();

        if (warp == 0) {
            Mat G = mat_identity();
            if (lane < NBLK / 32) {
#pragma unroll
                for (int i = 0; i < 9; i++) G.m[i] = s_final[lane * 9 + i];
            }
            G = warp_reduce_ordered<NBLK / 32>(G);
            if (lane == 0) {
                // initial state (INF, 0, INF) -> answer = P_total[1][1]
                d_out[0] = G.m[1 * 3 + 1];
                g_counter = 0u;  // reset for next graph replay
            }
        }
    }
}

extern "C" void kernel_launch(void* const* d_in, const int* in_sizes, int n_in,
                              void* d_out, int out_size) {
    const float* outp = (const float*)d_in[0];
    const float* tgt  = (const float*)d_in[1];
    int n = in_sizes[0];
    dtw_fused<<<NBLK, NTHR>>>(outp, tgt, (float*)d_out, n);
}